// round 10
// baseline (speedup 1.0000x reference)
#include <cuda_runtime.h>

// SparseEmbedding fused: scan one_hot [B,S,V] fp32 for each row's single
// nonzero; the finding thread immediately writes out[row] = val * weight[col].
// 1024 hits out of 51.5M elems -> copy work is noise overlapped with the scan.
// B=4,S=256,V=50257,D=768.

#define BS_ROWS 1024
#define V_DIM   50257
#define D_DIM   768
#define D4      (D_DIM / 4)

__device__ __forceinline__ uint4 ldcs16(const uint4* p)
{
    uint4 v;
    asm volatile("ld.global.cs.v4.u32 {%0,%1,%2,%3}, [%4];"
                 : "=r"(v.x), "=r"(v.y), "=r"(v.z), "=r"(v.w) : "l"(p));
    return v;
}

__device__ __forceinline__ bool nzu(uint4 v)
{
    return (v.x | v.y | v.z | v.w) != 0u;   // zeros are +0.0 = all-zero bits
}

// Cold path: executes 1024 times total across the whole grid.
__device__ __noinline__ void emit_row(const float4* __restrict__ w,
                                      float4* __restrict__ out,
                                      long e, float val)
{
    int row = (int)(e / V_DIM);
    int col = (int)(e - (long)row * V_DIM);
    const float4* src = w   + (long)col * D4;
    float4*       dst = out + (long)row * D4;
    #pragma unroll 8
    for (int t = 0; t < D4; t++) {
        float4 v = src[t];
        dst[t] = make_float4(v.x * val, v.y * val, v.z * val, v.w * val);
    }
}

__device__ __forceinline__ void check_hit(uint4 v, long i4,
                                          const float4* __restrict__ w,
                                          float4* __restrict__ out)
{
    unsigned bits[4] = {v.x, v.y, v.z, v.w};
    long base = i4 * 4;
    #pragma unroll
    for (int k = 0; k < 4; k++)
        if (bits[k] != 0u)
            emit_row(w, out, base + k, __uint_as_float(bits[k]));
}

__global__ void __launch_bounds__(256)
fused_scan_emit_kernel(const uint4* __restrict__ oh, long n4,
                       const float4* __restrict__ w,
                       float4* __restrict__ out)
{
    const long stride = (long)gridDim.x * blockDim.x;
    long i = (long)blockIdx.x * blockDim.x + threadIdx.x;

    // 8 independent streaming 16B loads in flight per lane.
    for (; i + 7 * stride < n4; i += 8 * stride) {
        uint4 v[8];
        #pragma unroll
        for (int k = 0; k < 8; k++) v[k] = ldcs16(oh + i + k * stride);
        #pragma unroll
        for (int k = 0; k < 8; k++)
            if (nzu(v[k])) check_hit(v[k], i + k * stride, w, out);
    }
    for (; i < n4; i += stride) {
        uint4 v = ldcs16(oh + i);
        if (nzu(v)) check_hit(v, i, w, out);
    }
}

extern "C" void kernel_launch(void* const* d_in, const int* in_sizes, int n_in,
                              void* d_out, int out_size)
{
    const uint4*  one_hot = (const uint4*)d_in[0];    // [B,S,V] fp32, flat
    const float4* weight  = (const float4*)d_in[1];   // [V,D] fp32
    float4*       out     = (float4*)d_out;           // [B,S,D] fp32

    const long n4 = (long)in_sizes[0] / 4;            // 12,865,792 uint4

    // One full wave: 8 CTAs/SM x 148 SMs, 256 threads.
    fused_scan_emit_kernel<<<1184, 256>>>(one_hot, n4, weight, out);
}